// round 1
// baseline (speedup 1.0000x reference)
#include <cuda_runtime.h>
#include <math.h>

#define NN 4096
#define FF 512
#define NH 8
#define DH 64
#define NC 40
#define LRA 0.2f

// ---------------- scratch (__device__ globals; no allocs) ----------------
__device__ float g_Wh [NN*FF];                 // layer1 Wh: [N][H*DH]
__device__ float g_f1 [NH*NN], g_f2 [NH*NN];
__device__ float g_e1p[NH*NN], g_e1n[NH*NN], g_e2p[NH*NN], g_e2n[NH*NN];
__device__ float g_h1 [NN*FF];                 // layer1 output (post-ELU, concat)
__device__ float g_Wh2[NN*NC];
__device__ float g_f1b[NN], g_f2b[NN], g_e1pb[NN], g_e1nb[NN], g_e2pb[NN], g_e2nb[NN];
__device__ float g_out2[NN*NC];

// ---------------- packed f32x2 helpers ----------------
__device__ __forceinline__ unsigned long long dup2(float a){
    unsigned long long r;
    asm("mov.b64 %0, {%1, %1};" : "=l"(r) : "f"(a));
    return r;
}
__device__ __forceinline__ void fma2(unsigned long long &d, unsigned long long a, unsigned long long b){
    asm("fma.rn.f32x2 %0, %1, %2, %3;" : "=l"(d) : "l"(a), "l"(b), "l"(d));
}
__device__ __forceinline__ float2 unpk(unsigned long long v){
    float2 r;
    asm("mov.b64 {%0, %1}, %2;" : "=f"(r.x), "=f"(r.y) : "l"(v));
    return r;
}
__device__ __forceinline__ float elu1(float v){
    return v > 0.f ? v : expm1f(v);
}

// ================= kernel 1: Wh = x @ W1 (64x64 tiles, f32x2) =================
__global__ void k_gemm1(const float* __restrict__ x, const float* __restrict__ W1){
    __shared__ float As[64][65];
    __shared__ float Bs[64][64];
    int tx = threadIdx.x, ty = threadIdx.y;
    int tid = ty*16+tx;
    int i0 = blockIdx.x*64;
    int h  = blockIdx.y;
    unsigned long long acc[4][2] = {};
    for (int k0 = 0; k0 < FF; k0 += 64){
        __syncthreads();
        #pragma unroll
        for (int t = 0; t < 16; t++){
            int idx = tid + t*256;
            int r = idx>>6, c = idx&63;
            As[r][c] = x [(size_t)(i0+r)*FF + k0 + c];
            Bs[r][c] = W1[(size_t)h*FF*DH + (size_t)(k0+r)*DH + c];
        }
        __syncthreads();
        #pragma unroll 16
        for (int kk = 0; kk < 64; kk++){
            unsigned long long a0 = dup2(As[tx   ][kk]);
            unsigned long long a1 = dup2(As[tx+16][kk]);
            unsigned long long a2 = dup2(As[tx+32][kk]);
            unsigned long long a3 = dup2(As[tx+48][kk]);
            const unsigned long long* wr = (const unsigned long long*)&Bs[kk][0];
            unsigned long long b0 = wr[ty*2+0];
            unsigned long long b1 = wr[ty*2+1];
            fma2(acc[0][0],a0,b0); fma2(acc[0][1],a0,b1);
            fma2(acc[1][0],a1,b0); fma2(acc[1][1],a1,b1);
            fma2(acc[2][0],a2,b0); fma2(acc[2][1],a2,b1);
            fma2(acc[3][0],a3,b0); fma2(acc[3][1],a3,b1);
        }
    }
    #pragma unroll
    for (int i = 0; i < 4; i++){
        int row = i0 + tx + 16*i;
        float2 v0 = unpk(acc[i][0]);
        float2 v1 = unpk(acc[i][1]);
        float4 v = make_float4(v0.x, v0.y, v1.x, v1.y);
        *(float4*)&g_Wh[(size_t)row*FF + h*DH + ty*4] = v;
    }
}

// ====== kernel 2: f1,f2 + separable exp tables, layer 1 (one warp/(h,i)) ======
__global__ void k_f1(const float* __restrict__ a1){
    int g = blockIdx.x*8 + (threadIdx.x>>5);     // [0, 8*4096)
    int lane = threadIdx.x & 31;
    int h = g >> 12;
    int i = g & (NN-1);
    const float* wh = g_Wh + (size_t)i*FF + h*DH;
    const float* as = a1 + h*2*DH;
    const float* ad = as + DH;
    float p1 = wh[lane]*as[lane] + wh[lane+32]*as[lane+32];
    float p2 = wh[lane]*ad[lane] + wh[lane+32]*ad[lane+32];
    #pragma unroll
    for (int o = 16; o; o >>= 1){
        p1 += __shfl_xor_sync(0xffffffffu, p1, o);
        p2 += __shfl_xor_sync(0xffffffffu, p2, o);
    }
    if (lane == 0){
        int k = h*NN + i;
        g_f1 [k] = p1;            g_f2 [k] = p2;
        g_e1p[k] = __expf(p1);    g_e1n[k] = __expf(LRA*p1);
        g_e2p[k] = __expf(p2);    g_e2n[k] = __expf(LRA*p2);
    }
}

// === kernel 3: layer-1 masked-softmax attention + P@Wh GEMM (64x64 tiles) ===
// grid (head fastest = x, row-block = y) so all heads share adj rows in L2.
__global__ void k_att1(const int* __restrict__ adjm){
    __shared__ float Ps[64][65];
    __shared__ float Ws[64][64];
    __shared__ float f1s[64], e1ps[64], e1ns[64];
    __shared__ float f2s[64], e2ps[64], e2ns[64];
    __shared__ float denomS[64];
    int tx = threadIdx.x, ty = threadIdx.y;
    int tid = ty*16 + tx;              // 0..127
    int h  = blockIdx.x;
    int i0 = blockIdx.y*64;
    if (tid < 64){
        int i = i0 + tid;
        f1s [tid] = g_f1 [h*NN+i];
        e1ps[tid] = g_e1p[h*NN+i];
        e1ns[tid] = g_e1n[h*NN+i];
        denomS[tid] = 0.f;
    }
    unsigned long long acc[4][4] = {};
    for (int j0 = 0; j0 < NN; j0 += 64){
        __syncthreads();                               // prev MAC done
        if (tid < 64){
            int j = j0 + tid;
            f2s [tid] = g_f2 [h*NN+j];
            e2ps[tid] = g_e2p[h*NN+j];
            e2ns[tid] = g_e2n[h*NN+j];
        }
        #pragma unroll 8
        for (int t = 0; t < 32; t++){
            int idx = tid + t*128;
            int r = idx>>6, c = idx&63;
            Ws[r][c] = g_Wh[(size_t)(j0+r)*FF + h*DH + c];
        }
        __syncthreads();                               // f2 stage ready
        #pragma unroll 8
        for (int t = 0; t < 32; t++){
            int idx = tid + t*128;
            int r = idx>>6, jj = idx&63;
            int a = adjm[(size_t)(i0+r)*NN + j0 + jj];
            float s = f1s[r] + f2s[jj];
            float v = 0.f;
            if (a) v = (s >= 0.f) ? e1ps[r]*e2ps[jj] : e1ns[r]*e2ns[jj];
            Ps[r][jj] = v;
        }
        __syncthreads();                               // P tile ready
        if (tid < 64){
            float sm = 0.f;
            #pragma unroll 16
            for (int jj = 0; jj < 64; jj++) sm += Ps[tid][jj];
            denomS[tid] += sm;
        }
        #pragma unroll 8
        for (int kk = 0; kk < 64; kk++){
            unsigned long long a0 = dup2(Ps[tx   ][kk]);
            unsigned long long a1 = dup2(Ps[tx+16][kk]);
            unsigned long long a2 = dup2(Ps[tx+32][kk]);
            unsigned long long a3 = dup2(Ps[tx+48][kk]);
            const unsigned long long* wr = (const unsigned long long*)&Ws[kk][0];
            unsigned long long b0 = wr[ty*4+0];
            unsigned long long b1 = wr[ty*4+1];
            unsigned long long b2 = wr[ty*4+2];
            unsigned long long b3 = wr[ty*4+3];
            fma2(acc[0][0],a0,b0); fma2(acc[0][1],a0,b1); fma2(acc[0][2],a0,b2); fma2(acc[0][3],a0,b3);
            fma2(acc[1][0],a1,b0); fma2(acc[1][1],a1,b1); fma2(acc[1][2],a1,b2); fma2(acc[1][3],a1,b3);
            fma2(acc[2][0],a2,b0); fma2(acc[2][1],a2,b1); fma2(acc[2][2],a2,b2); fma2(acc[2][3],a2,b3);
            fma2(acc[3][0],a3,b0); fma2(acc[3][1],a3,b1); fma2(acc[3][2],a3,b2); fma2(acc[3][3],a3,b3);
        }
    }
    __syncthreads();
    #pragma unroll
    for (int i = 0; i < 4; i++){
        int row = tx + 16*i;
        float inv = 1.0f / denomS[row];
        float* op = &g_h1[(size_t)(i0+row)*FF + h*DH + ty*8];
        #pragma unroll
        for (int jp = 0; jp < 4; jp++){
            float2 v = unpk(acc[i][jp]);
            v.x = elu1(v.x * inv);
            v.y = elu1(v.y * inv);
            *(float2*)(op + 2*jp) = v;
        }
    }
}

// ================= kernel 4: Wh2 = h1 @ Wo (4096x512x40) =================
__global__ void k_gemm2(const float* __restrict__ Wo){
    __shared__ float As[64][65];
    __shared__ float Bs[64][40];
    int tx = threadIdx.x, ty = threadIdx.y;
    int tid = ty*16+tx;                // block (16,10) = 160
    int i0 = blockIdx.x*64;
    float acc[4][4] = {};
    for (int k0 = 0; k0 < FF; k0 += 64){
        __syncthreads();
        for (int idx = tid; idx < 4096; idx += 160){
            int r = idx>>6, c = idx&63;
            As[r][c] = g_h1[(size_t)(i0+r)*FF + k0 + c];
        }
        for (int idx = tid; idx < 64*NC; idx += 160){
            int r = idx/NC, c = idx - r*NC;
            Bs[r][c] = Wo[(size_t)(k0+r)*NC + c];
        }
        __syncthreads();
        #pragma unroll 8
        for (int kk = 0; kk < 64; kk++){
            float a0 = As[tx][kk], a1 = As[tx+16][kk], a2 = As[tx+32][kk], a3 = As[tx+48][kk];
            float4 b = *(const float4*)&Bs[kk][ty*4];
            acc[0][0] += a0*b.x; acc[0][1] += a0*b.y; acc[0][2] += a0*b.z; acc[0][3] += a0*b.w;
            acc[1][0] += a1*b.x; acc[1][1] += a1*b.y; acc[1][2] += a1*b.z; acc[1][3] += a1*b.w;
            acc[2][0] += a2*b.x; acc[2][1] += a2*b.y; acc[2][2] += a2*b.z; acc[2][3] += a2*b.w;
            acc[3][0] += a3*b.x; acc[3][1] += a3*b.y; acc[3][2] += a3*b.z; acc[3][3] += a3*b.w;
        }
    }
    #pragma unroll
    for (int i = 0; i < 4; i++){
        int row = i0 + tx + 16*i;
        float4 v = make_float4(acc[i][0], acc[i][1], acc[i][2], acc[i][3]);
        *(float4*)&g_Wh2[(size_t)row*NC + ty*4] = v;
    }
}

// ====== kernel 5: layer-2 f/e tables (one warp per node, 40 dims) ======
__global__ void k_f2b(const float* __restrict__ ao){
    int g = blockIdx.x*8 + (threadIdx.x>>5);   // [0, 4096)
    int lane = threadIdx.x & 31;
    const float* w = g_Wh2 + (size_t)g*NC;
    float v  = w[lane];
    float p1 = v*ao[lane];
    float p2 = v*ao[NC+lane];
    if (lane < 8){
        float v2 = w[32+lane];
        p1 += v2*ao[32+lane];
        p2 += v2*ao[NC+32+lane];
    }
    #pragma unroll
    for (int o = 16; o; o >>= 1){
        p1 += __shfl_xor_sync(0xffffffffu, p1, o);
        p2 += __shfl_xor_sync(0xffffffffu, p2, o);
    }
    if (lane == 0){
        g_f1b [g] = p1;          g_f2b [g] = p2;
        g_e1pb[g] = __expf(p1);  g_e1nb[g] = __expf(LRA*p1);
        g_e2pb[g] = __expf(p2);  g_e2nb[g] = __expf(LRA*p2);
    }
}

// === kernel 6: layer-2 attention (32-row tiles, D=40) ===
__global__ void k_att2(const int* __restrict__ adjm){
    __shared__ float Ps[32][33];
    __shared__ float Ws[64][40];
    __shared__ float f1s[32], e1ps[32], e1ns[32];
    __shared__ float f2s[64], e2ps[64], e2ns[64];
    __shared__ float denomS[32];
    int tx = threadIdx.x, ty = threadIdx.y;
    int tid = ty*16 + tx;              // block (16,10) = 160
    int i0 = blockIdx.x*32;
    if (tid < 32){
        f1s [tid] = g_f1b [i0+tid];
        e1ps[tid] = g_e1pb[i0+tid];
        e1ns[tid] = g_e1nb[i0+tid];
        denomS[tid] = 0.f;
    }
    unsigned long long acc[2][2] = {};
    for (int j0 = 0; j0 < NN; j0 += 64){
        __syncthreads();
        if (tid < 64){
            f2s [tid] = g_f2b [j0+tid];
            e2ps[tid] = g_e2pb[j0+tid];
            e2ns[tid] = g_e2nb[j0+tid];
        }
        for (int idx = tid; idx < 64*NC; idx += 160){
            int r = idx/NC, c = idx - r*NC;
            Ws[r][c] = g_Wh2[(size_t)(j0+r)*NC + c];
        }
        __syncthreads();
        for (int idx = tid; idx < 32*64; idx += 160){
            int r = idx>>6, jj = idx&63;
            int a = adjm[(size_t)(i0+r)*NN + j0 + jj];
            float s = f1s[r] + f2s[jj];
            float v = 0.f;
            if (a) v = (s >= 0.f) ? e1ps[r]*e2ps[jj] : e1ns[r]*e2ns[jj];
            Ps[r][jj] = v;
        }
        __syncthreads();
        if (tid < 32){
            float sm = 0.f;
            #pragma unroll 16
            for (int jj = 0; jj < 64; jj++) sm += Ps[tid][jj];
            denomS[tid] += sm;
        }
        #pragma unroll 8
        for (int kk = 0; kk < 64; kk++){
            unsigned long long a0 = dup2(Ps[tx   ][kk]);
            unsigned long long a1 = dup2(Ps[tx+16][kk]);
            const unsigned long long* wr = (const unsigned long long*)&Ws[kk][0];
            unsigned long long b0 = wr[ty*2+0];
            unsigned long long b1 = wr[ty*2+1];
            fma2(acc[0][0],a0,b0); fma2(acc[0][1],a0,b1);
            fma2(acc[1][0],a1,b0); fma2(acc[1][1],a1,b1);
        }
    }
    __syncthreads();
    #pragma unroll
    for (int i = 0; i < 2; i++){
        int row = tx + 16*i;
        float inv = 1.0f / denomS[row];
        float* op = &g_out2[(size_t)(i0+row)*NC + ty*4];
        #pragma unroll
        for (int jp = 0; jp < 2; jp++){
            float2 v = unpk(acc[i][jp]);
            v.x *= inv; v.y *= inv;
            *(float2*)(op + 2*jp) = v;
        }
    }
}

// ====== kernel 7: outer ELU + log_softmax (one warp per row) ======
__global__ void k_final(float* __restrict__ out){
    int w = threadIdx.x>>5, lane = threadIdx.x & 31;
    int i = blockIdx.x*8 + w;
    float v0 = elu1(g_out2[(size_t)i*NC + lane]);
    float v1 = (lane < 8) ? elu1(g_out2[(size_t)i*NC + 32 + lane]) : -1e30f;
    float m = fmaxf(v0, v1);
    #pragma unroll
    for (int o = 16; o; o >>= 1) m = fmaxf(m, __shfl_xor_sync(0xffffffffu, m, o));
    float s = expf(v0 - m) + ((lane < 8) ? expf(v1 - m) : 0.f);
    #pragma unroll
    for (int o = 16; o; o >>= 1) s += __shfl_xor_sync(0xffffffffu, s, o);
    float ls = m + logf(s);
    out[(size_t)i*NC + lane] = v0 - ls;
    if (lane < 8) out[(size_t)i*NC + 32 + lane] = v1 - ls;
}

// ============================== launch ==============================
extern "C" void kernel_launch(void* const* d_in, const int* in_sizes, int n_in,
                              void* d_out, int out_size){
    const float* x  = (const float*)d_in[0];
    const int*   adj= (const int*)  d_in[1];
    const float* W1 = (const float*)d_in[2];
    const float* a1 = (const float*)d_in[3];
    const float* Wo = (const float*)d_in[4];
    const float* ao = (const float*)d_in[5];
    float* out = (float*)d_out;

    const int* adj1 = adj + (size_t)NN*NN;   // adj[1] -> layer 1
    const int* adj0 = adj;                   // adj[0] -> layer 2

    k_gemm1<<<dim3(64, 8), dim3(16, 16)>>>(x, W1);
    k_f1   <<<4096, 256>>>(a1);
    k_att1 <<<dim3(8, 64), dim3(16, 8)>>>(adj1);   // head fastest -> adj L2 reuse
    k_gemm2<<<64, dim3(16, 10)>>>(Wo);
    k_f2b  <<<512, 256>>>(ao);
    k_att2 <<<128, dim3(16, 10)>>>(adj0);
    k_final<<<512, 256>>>(out);
}

// round 2
// speedup vs baseline: 1.0154x; 1.0154x over previous
#include <cuda_runtime.h>
#include <math.h>

#define NN 4096
#define FF 512
#define NH 8
#define DH 64
#define NC 40
#define LRA 0.2f

// ---------------- scratch (__device__ globals; no allocs) ----------------
__device__ float g_Wh [NN*FF];                 // layer1 Wh: [N][H*DH]
__device__ float g_f1 [NH*NN], g_f2 [NH*NN];
__device__ float g_e1p[NH*NN], g_e1n[NH*NN], g_e2p[NH*NN], g_e2n[NH*NN];
__device__ float g_h1 [NN*FF];                 // layer1 output (post-ELU, concat)
__device__ float g_Wh2[NN*NC];
__device__ float g_f1b[NN], g_f2b[NN], g_e1pb[NN], g_e1nb[NN], g_e2pb[NN], g_e2nb[NN];
__device__ float g_out2[NN*NC];

// ---------------- packed f32x2 helpers ----------------
__device__ __forceinline__ unsigned long long dup2(float a){
    unsigned long long r;
    asm("mov.b64 %0, {%1, %1};" : "=l"(r) : "f"(a));
    return r;
}
__device__ __forceinline__ void fma2(unsigned long long &d, unsigned long long a, unsigned long long b){
    asm("fma.rn.f32x2 %0, %1, %2, %3;" : "=l"(d) : "l"(a), "l"(b), "l"(d));
}
__device__ __forceinline__ float2 unpk(unsigned long long v){
    float2 r;
    asm("mov.b64 {%0, %1}, %2;" : "=f"(r.x), "=f"(r.y) : "l"(v));
    return r;
}
__device__ __forceinline__ float elu1(float v){
    return v > 0.f ? v : expm1f(v);
}

// ================= kernel 1: Wh = x @ W1 (64x64 tiles, f32x2) =================
__global__ void k_gemm1(const float* __restrict__ x, const float* __restrict__ W1){
    __shared__ float As[64][65];
    __shared__ float Bs[64][64];
    int tx = threadIdx.x, ty = threadIdx.y;
    int tid = ty*16+tx;
    int i0 = blockIdx.x*64;
    int h  = blockIdx.y;
    unsigned long long acc[4][2] = {};
    for (int k0 = 0; k0 < FF; k0 += 64){
        __syncthreads();
        #pragma unroll
        for (int t = 0; t < 16; t++){
            int idx = tid + t*256;
            int r = idx>>6, c = idx&63;
            As[r][c] = x [(size_t)(i0+r)*FF + k0 + c];
            Bs[r][c] = W1[(size_t)h*FF*DH + (size_t)(k0+r)*DH + c];
        }
        __syncthreads();
        #pragma unroll 16
        for (int kk = 0; kk < 64; kk++){
            unsigned long long a0 = dup2(As[tx   ][kk]);
            unsigned long long a1 = dup2(As[tx+16][kk]);
            unsigned long long a2 = dup2(As[tx+32][kk]);
            unsigned long long a3 = dup2(As[tx+48][kk]);
            const unsigned long long* wr = (const unsigned long long*)&Bs[kk][0];
            unsigned long long b0 = wr[ty*2+0];
            unsigned long long b1 = wr[ty*2+1];
            fma2(acc[0][0],a0,b0); fma2(acc[0][1],a0,b1);
            fma2(acc[1][0],a1,b0); fma2(acc[1][1],a1,b1);
            fma2(acc[2][0],a2,b0); fma2(acc[2][1],a2,b1);
            fma2(acc[3][0],a3,b0); fma2(acc[3][1],a3,b1);
        }
    }
    #pragma unroll
    for (int i = 0; i < 4; i++){
        int row = i0 + tx + 16*i;
        float2 v0 = unpk(acc[i][0]);
        float2 v1 = unpk(acc[i][1]);
        float4 v = make_float4(v0.x, v0.y, v1.x, v1.y);
        *(float4*)&g_Wh[(size_t)row*FF + h*DH + ty*4] = v;
    }
}

// ====== kernel 2: f1,f2 + separable exp tables, layer 1 (one warp/(h,i)) ======
__global__ void k_f1(const float* __restrict__ a1){
    int g = blockIdx.x*8 + (threadIdx.x>>5);     // [0, 8*4096)
    int lane = threadIdx.x & 31;
    int h = g >> 12;
    int i = g & (NN-1);
    const float* wh = g_Wh + (size_t)i*FF + h*DH;
    const float* as = a1 + h*2*DH;
    const float* ad = as + DH;
    float p1 = wh[lane]*as[lane] + wh[lane+32]*as[lane+32];
    float p2 = wh[lane]*ad[lane] + wh[lane+32]*ad[lane+32];
    #pragma unroll
    for (int o = 16; o; o >>= 1){
        p1 += __shfl_xor_sync(0xffffffffu, p1, o);
        p2 += __shfl_xor_sync(0xffffffffu, p2, o);
    }
    if (lane == 0){
        int k = h*NN + i;
        g_f1 [k] = p1;            g_f2 [k] = p2;
        g_e1p[k] = __expf(p1);    g_e1n[k] = __expf(LRA*p1);
        g_e2p[k] = __expf(p2);    g_e2n[k] = __expf(LRA*p2);
    }
}

// === kernel 3: layer-1 masked-softmax attention + P@Wh GEMM (64x64 tiles) ===
// grid (head fastest = x, row-block = y) so all heads share adj rows in L2.
__global__ void k_att1(const int* __restrict__ adjm){
    __shared__ float Ps[64][65];
    __shared__ float Ws[64][64];
    __shared__ float f1s[64], e1ps[64], e1ns[64];
    __shared__ float f2s[64], e2ps[64], e2ns[64];
    __shared__ float denomS[64];
    int tx = threadIdx.x, ty = threadIdx.y;
    int tid = ty*16 + tx;              // 0..127
    int h  = blockIdx.x;
    int i0 = blockIdx.y*64;
    if (tid < 64){
        int i = i0 + tid;
        f1s [tid] = g_f1 [h*NN+i];
        e1ps[tid] = g_e1p[h*NN+i];
        e1ns[tid] = g_e1n[h*NN+i];
        denomS[tid] = 0.f;
    }
    unsigned long long acc[4][4] = {};
    for (int j0 = 0; j0 < NN; j0 += 64){
        __syncthreads();                               // prev MAC done
        if (tid < 64){
            int j = j0 + tid;
            f2s [tid] = g_f2 [h*NN+j];
            e2ps[tid] = g_e2p[h*NN+j];
            e2ns[tid] = g_e2n[h*NN+j];
        }
        #pragma unroll 8
        for (int t = 0; t < 32; t++){
            int idx = tid + t*128;
            int r = idx>>6, c = idx&63;
            Ws[r][c] = g_Wh[(size_t)(j0+r)*FF + h*DH + c];
        }
        __syncthreads();                               // f2 stage ready
        #pragma unroll 8
        for (int t = 0; t < 32; t++){
            int idx = tid + t*128;
            int r = idx>>6, jj = idx&63;
            int a = adjm[(size_t)(i0+r)*NN + j0 + jj];
            float s = f1s[r] + f2s[jj];
            float v = 0.f;
            if (a) v = (s >= 0.f) ? e1ps[r]*e2ps[jj] : e1ns[r]*e2ns[jj];
            Ps[r][jj] = v;
        }
        __syncthreads();                               // P tile ready
        if (tid < 64){
            float sm = 0.f;
            #pragma unroll 16
            for (int jj = 0; jj < 64; jj++) sm += Ps[tid][jj];
            denomS[tid] += sm;
        }
        #pragma unroll 8
        for (int kk = 0; kk < 64; kk++){
            unsigned long long a0 = dup2(Ps[tx   ][kk]);
            unsigned long long a1 = dup2(Ps[tx+16][kk]);
            unsigned long long a2 = dup2(Ps[tx+32][kk]);
            unsigned long long a3 = dup2(Ps[tx+48][kk]);
            const unsigned long long* wr = (const unsigned long long*)&Ws[kk][0];
            unsigned long long b0 = wr[ty*4+0];
            unsigned long long b1 = wr[ty*4+1];
            unsigned long long b2 = wr[ty*4+2];
            unsigned long long b3 = wr[ty*4+3];
            fma2(acc[0][0],a0,b0); fma2(acc[0][1],a0,b1); fma2(acc[0][2],a0,b2); fma2(acc[0][3],a0,b3);
            fma2(acc[1][0],a1,b0); fma2(acc[1][1],a1,b1); fma2(acc[1][2],a1,b2); fma2(acc[1][3],a1,b3);
            fma2(acc[2][0],a2,b0); fma2(acc[2][1],a2,b1); fma2(acc[2][2],a2,b2); fma2(acc[2][3],a2,b3);
            fma2(acc[3][0],a3,b0); fma2(acc[3][1],a3,b1); fma2(acc[3][2],a3,b2); fma2(acc[3][3],a3,b3);
        }
    }
    __syncthreads();
    #pragma unroll
    for (int i = 0; i < 4; i++){
        int row = tx + 16*i;
        float inv = 1.0f / denomS[row];
        float* op = &g_h1[(size_t)(i0+row)*FF + h*DH + ty*8];
        #pragma unroll
        for (int jp = 0; jp < 4; jp++){
            float2 v = unpk(acc[i][jp]);
            v.x = elu1(v.x * inv);
            v.y = elu1(v.y * inv);
            *(float2*)(op + 2*jp) = v;
        }
    }
}

// ================= kernel 4: Wh2 = h1 @ Wo (4096x512x40) =================
__global__ void k_gemm2(const float* __restrict__ Wo){
    __shared__ float As[64][65];
    __shared__ float Bs[64][40];
    int tx = threadIdx.x, ty = threadIdx.y;
    int tid = ty*16+tx;                // block (16,10) = 160
    int i0 = blockIdx.x*64;
    float acc[4][4] = {};
    for (int k0 = 0; k0 < FF; k0 += 64){
        __syncthreads();
        for (int idx = tid; idx < 4096; idx += 160){
            int r = idx>>6, c = idx&63;
            As[r][c] = g_h1[(size_t)(i0+r)*FF + k0 + c];
        }
        for (int idx = tid; idx < 64*NC; idx += 160){
            int r = idx/NC, c = idx - r*NC;
            Bs[r][c] = Wo[(size_t)(k0+r)*NC + c];
        }
        __syncthreads();
        #pragma unroll 8
        for (int kk = 0; kk < 64; kk++){
            float a0 = As[tx][kk], a1 = As[tx+16][kk], a2 = As[tx+32][kk], a3 = As[tx+48][kk];
            float4 b = *(const float4*)&Bs[kk][ty*4];
            acc[0][0] += a0*b.x; acc[0][1] += a0*b.y; acc[0][2] += a0*b.z; acc[0][3] += a0*b.w;
            acc[1][0] += a1*b.x; acc[1][1] += a1*b.y; acc[1][2] += a1*b.z; acc[1][3] += a1*b.w;
            acc[2][0] += a2*b.x; acc[2][1] += a2*b.y; acc[2][2] += a2*b.z; acc[2][3] += a2*b.w;
            acc[3][0] += a3*b.x; acc[3][1] += a3*b.y; acc[3][2] += a3*b.z; acc[3][3] += a3*b.w;
        }
    }
    #pragma unroll
    for (int i = 0; i < 4; i++){
        int row = i0 + tx + 16*i;
        float4 v = make_float4(acc[i][0], acc[i][1], acc[i][2], acc[i][3]);
        *(float4*)&g_Wh2[(size_t)row*NC + ty*4] = v;
    }
}

// ====== kernel 5: layer-2 f/e tables (one warp per node, 40 dims) ======
__global__ void k_f2b(const float* __restrict__ ao){
    int g = blockIdx.x*8 + (threadIdx.x>>5);   // [0, 4096)
    int lane = threadIdx.x & 31;
    const float* w = g_Wh2 + (size_t)g*NC;
    float v  = w[lane];
    float p1 = v*ao[lane];
    float p2 = v*ao[NC+lane];
    if (lane < 8){
        float v2 = w[32+lane];
        p1 += v2*ao[32+lane];
        p2 += v2*ao[NC+32+lane];
    }
    #pragma unroll
    for (int o = 16; o; o >>= 1){
        p1 += __shfl_xor_sync(0xffffffffu, p1, o);
        p2 += __shfl_xor_sync(0xffffffffu, p2, o);
    }
    if (lane == 0){
        g_f1b [g] = p1;          g_f2b [g] = p2;
        g_e1pb[g] = __expf(p1);  g_e1nb[g] = __expf(LRA*p1);
        g_e2pb[g] = __expf(p2);  g_e2nb[g] = __expf(LRA*p2);
    }
}

// === kernel 6: layer-2 attention (32-row tiles, D=40) ===
__global__ void k_att2(const int* __restrict__ adjm){
    __shared__ float Ps[32][33];
    __shared__ float Ws[64][40];
    __shared__ float f1s[32], e1ps[32], e1ns[32];
    __shared__ float f2s[64], e2ps[64], e2ns[64];
    __shared__ float denomS[32];
    int tx = threadIdx.x, ty = threadIdx.y;
    int tid = ty*16 + tx;              // block (16,10) = 160
    int i0 = blockIdx.x*32;
    if (tid < 32){
        f1s [tid] = g_f1b [i0+tid];
        e1ps[tid] = g_e1pb[i0+tid];
        e1ns[tid] = g_e1nb[i0+tid];
        denomS[tid] = 0.f;
    }
    unsigned long long acc[2][2] = {};
    for (int j0 = 0; j0 < NN; j0 += 64){
        __syncthreads();
        if (tid < 64){
            f2s [tid] = g_f2b [j0+tid];
            e2ps[tid] = g_e2pb[j0+tid];
            e2ns[tid] = g_e2nb[j0+tid];
        }
        for (int idx = tid; idx < 64*NC; idx += 160){
            int r = idx/NC, c = idx - r*NC;
            Ws[r][c] = g_Wh2[(size_t)(j0+r)*NC + c];
        }
        __syncthreads();
        for (int idx = tid; idx < 32*64; idx += 160){
            int r = idx>>6, jj = idx&63;
            int a = adjm[(size_t)(i0+r)*NN + j0 + jj];
            float s = f1s[r] + f2s[jj];
            float v = 0.f;
            if (a) v = (s >= 0.f) ? e1ps[r]*e2ps[jj] : e1ns[r]*e2ns[jj];
            Ps[r][jj] = v;
        }
        __syncthreads();
        if (tid < 32){
            float sm = 0.f;
            #pragma unroll 16
            for (int jj = 0; jj < 64; jj++) sm += Ps[tid][jj];
            denomS[tid] += sm;
        }
        #pragma unroll 8
        for (int kk = 0; kk < 64; kk++){
            unsigned long long a0 = dup2(Ps[tx   ][kk]);
            unsigned long long a1 = dup2(Ps[tx+16][kk]);
            const unsigned long long* wr = (const unsigned long long*)&Ws[kk][0];
            unsigned long long b0 = wr[ty*2+0];
            unsigned long long b1 = wr[ty*2+1];
            fma2(acc[0][0],a0,b0); fma2(acc[0][1],a0,b1);
            fma2(acc[1][0],a1,b0); fma2(acc[1][1],a1,b1);
        }
    }
    __syncthreads();
    #pragma unroll
    for (int i = 0; i < 2; i++){
        int row = tx + 16*i;
        float inv = 1.0f / denomS[row];
        float* op = &g_out2[(size_t)(i0+row)*NC + ty*4];
        #pragma unroll
        for (int jp = 0; jp < 2; jp++){
            float2 v = unpk(acc[i][jp]);
            v.x *= inv; v.y *= inv;
            *(float2*)(op + 2*jp) = v;
        }
    }
}

// ====== kernel 7: outer ELU + log_softmax (one warp per row) ======
__global__ void k_final(float* __restrict__ out){
    int w = threadIdx.x>>5, lane = threadIdx.x & 31;
    int i = blockIdx.x*8 + w;
    float v0 = elu1(g_out2[(size_t)i*NC + lane]);
    float v1 = (lane < 8) ? elu1(g_out2[(size_t)i*NC + 32 + lane]) : -1e30f;
    float m = fmaxf(v0, v1);
    #pragma unroll
    for (int o = 16; o; o >>= 1) m = fmaxf(m, __shfl_xor_sync(0xffffffffu, m, o));
    float s = expf(v0 - m) + ((lane < 8) ? expf(v1 - m) : 0.f);
    #pragma unroll
    for (int o = 16; o; o >>= 1) s += __shfl_xor_sync(0xffffffffu, s, o);
    float ls = m + logf(s);
    out[(size_t)i*NC + lane] = v0 - ls;
    if (lane < 8) out[(size_t)i*NC + 32 + lane] = v1 - ls;
}

// ============================== launch ==============================
extern "C" void kernel_launch(void* const* d_in, const int* in_sizes, int n_in,
                              void* d_out, int out_size){
    const float* x  = (const float*)d_in[0];
    const int*   adj= (const int*)  d_in[1];
    const float* W1 = (const float*)d_in[2];
    const float* a1 = (const float*)d_in[3];
    const float* Wo = (const float*)d_in[4];
    const float* ao = (const float*)d_in[5];
    float* out = (float*)d_out;

    const int* adj1 = adj + (size_t)NN*NN;   // adj[1] -> layer 1
    const int* adj0 = adj;                   // adj[0] -> layer 2

    k_gemm1<<<dim3(64, 8), dim3(16, 16)>>>(x, W1);
    k_f1   <<<4096, 256>>>(a1);
    k_att1 <<<dim3(8, 64), dim3(16, 8)>>>(adj1);   // head fastest -> adj L2 reuse
    k_gemm2<<<64, dim3(16, 10)>>>(Wo);
    k_f2b  <<<512, 256>>>(ao);
    k_att2 <<<128, dim3(16, 10)>>>(adj0);
    k_final<<<512, 256>>>(out);
}